// round 8
// baseline (speedup 1.0000x reference)
#include <cuda_runtime.h>
#include <cuda_fp16.h>

#define N_NODES 100000
#define N_EDGES 1600000
#define IN_CH 128
#define ED_CH 32
#define HEADS 4
#define CH 32
#define HC 128
#define NEG_SLOPE 0.2f
#define SCAN_BLK 1024
#define N_SCAN_BLKS ((N_NODES + SCAN_BLK - 1) / SCAN_BLK)   // 98

// ---------------- scratch (no runtime allocation allowed) ----------------
__device__ __half g_xh_h[N_NODES * HC];         // 25.6 MB fp16 xh, [N,H,C]
__device__ float g_asrc[N_NODES * HEADS];
__device__ float g_adst[N_NODES * HEADS];
__device__ float g_weff[ED_CH * HEADS];         // folded W_edge @ att_edge
__device__ uint2 g_Wp[16 * 16 * 32];            // W packed as tf32 B-fragments
__device__ float4 g_aedge[N_EDGES];             // 25.6 MB a_edge per edge (4 heads)
__device__ uint4 g_rec[N_EDGES];                // {src, ev01(h2), ev23(h2), 0} by dst
__device__ int   g_count[N_NODES];
__device__ int   g_rowptr[N_NODES + 1];
__device__ int   g_cursor[N_NODES];
__device__ int   g_bsum[N_SCAN_BLKS];
__device__ int   g_boff[N_SCAN_BLKS];

__device__ __forceinline__ unsigned tf32r(float f) {
    unsigned r;
    asm("cvt.rna.tf32.f32 %0, %1;" : "=r"(r) : "f"(f));
    return r;
}

__device__ __forceinline__ void mma_tf32(float c[4], unsigned a0, unsigned a1,
                                         unsigned a2, unsigned a3,
                                         unsigned b0, unsigned b1) {
    asm volatile(
        "mma.sync.aligned.m16n8k8.row.col.f32.tf32.tf32.f32 "
        "{%0,%1,%2,%3},{%4,%5,%6,%7},{%8,%9},{%0,%1,%2,%3};"
        : "+f"(c[0]), "+f"(c[1]), "+f"(c[2]), "+f"(c[3])
        : "r"(a0), "r"(a1), "r"(a2), "r"(a3), "r"(b0), "r"(b1));
}

// ---------------- init: zero edge counts ------------------------------------
__global__ void k_init() {
    int i = blockIdx.x * blockDim.x + threadIdx.x;
    if (i < N_NODES) g_count[i] = 0;
}

// ---------------- degree count: 4 edges per thread via int4 -----------------
__global__ __launch_bounds__(256) void k_count(const int* __restrict__ ei) {
    int i = blockIdx.x * 256 + threadIdx.x;        // int4 index
    if (i * 4 < N_EDGES) {
        int4 d4 = *(const int4*)(ei + N_EDGES + i * 4);
        atomicAdd(&g_count[d4.x], 1);
        atomicAdd(&g_count[d4.y], 1);
        atomicAdd(&g_count[d4.z], 1);
        atomicAdd(&g_count[d4.w], 1);
    }
}

// ---------------- w_eff only (aux2 path, before k_aedge) --------------------
__global__ void k_weff(const float* __restrict__ W_edge,
                       const float* __restrict__ att_edge) {
    int t = threadIdx.x;           // 128 threads
    int d = t >> 2, h = t & 3;
    float s = 0.f;
    #pragma unroll
    for (int c = 0; c < CH; c++)
        s += W_edge[d * HC + h * CH + c] * att_edge[h * CH + c];
    g_weff[d * HEADS + h] = s;
}

// ---------------- W pack (main path, before gemm) ---------------------------
__global__ __launch_bounds__(256) void k_wpack(const float* __restrict__ W) {
    int t = blockIdx.x * 256 + threadIdx.x;  // 0..8191
    int lane = t & 31;
    int n = (t >> 5) & 15;
    int kk = t >> 9;
    int krow = 8 * kk + (lane & 3);
    int col = 8 * n + (lane >> 2);
    uint2 bb;
    bb.x = tf32r(W[krow * HC + col]);
    bb.y = tf32r(W[(krow + 4) * HC + col]);
    g_Wp[t] = bb;
}

// ---------------- a_edge = ea @ w_eff (aux2, overlaps gemm) -----------------
__global__ __launch_bounds__(256) void k_aedge(const float* __restrict__ ea) {
    __shared__ float sEA[256][33];
    __shared__ float4 sW[32];
    int tid = threadIdx.x;
    int e0  = blockIdx.x * 256;

    if (tid < 32) sW[tid] = *(const float4*)(g_weff + tid * 4);

    const float4* gsrc = (const float4*)(ea + (size_t)e0 * ED_CH);
    #pragma unroll
    for (int k = 0; k < 8; k++) {
        int idx = tid + k * 256;
        float4 v = gsrc[idx];
        int row = idx >> 3;
        int col = (idx & 7) * 4;
        sEA[row][col + 0] = v.x; sEA[row][col + 1] = v.y;
        sEA[row][col + 2] = v.z; sEA[row][col + 3] = v.w;
    }
    __syncthreads();

    float s0 = 0.f, s1 = 0.f, s2 = 0.f, s3 = 0.f;
    #pragma unroll
    for (int d = 0; d < 32; d++) {
        float v = sEA[tid][d];
        float4 w = sW[d];
        s0 += v * w.x; s1 += v * w.y; s2 += v * w.z; s3 += v * w.w;
    }
    g_aedge[e0 + tid] = make_float4(s0, s1, s2, s3);
}

// ---------------- xh = x @ W via tf32 mma + fused a_src/a_dst ---------------
__global__ __launch_bounds__(256) void k_gemm(const float* __restrict__ x,
                                              const float* __restrict__ att_src,
                                              const float* __restrict__ att_dst) {
    int tid  = threadIdx.x;
    int warp = tid >> 5;
    int lane = tid & 31;
    int grp  = lane >> 2;      // 0..7 (row within fragment)
    int q    = lane & 3;       // quad id (col group)

    int r0  = blockIdx.x * 128 + warp * 16;
    int rlo = r0 + grp;
    int rhi = rlo + 8;
    int rloL = rlo < N_NODES ? rlo : N_NODES - 1;
    int rhiL = rhi < N_NODES ? rhi : N_NODES - 1;
    const float* xlo = x + (size_t)rloL * IN_CH;
    const float* xhi = x + (size_t)rhiL * IN_CH;

    float c[16][4];
    #pragma unroll
    for (int n = 0; n < 16; n++) { c[n][0] = c[n][1] = c[n][2] = c[n][3] = 0.f; }

    #pragma unroll
    for (int kk = 0; kk < 16; kk++) {
        int k0 = 8 * kk;
        unsigned a0 = tf32r(__ldg(xlo + k0 + q));
        unsigned a1 = tf32r(__ldg(xhi + k0 + q));
        unsigned a2 = tf32r(__ldg(xlo + k0 + q + 4));
        unsigned a3 = tf32r(__ldg(xhi + k0 + q + 4));
        const uint2* wp = g_Wp + (size_t)kk * 16 * 32 + lane;
        #pragma unroll
        for (int n = 0; n < 16; n++) {
            uint2 b = __ldg(wp + n * 32);
            mma_tf32(c[n], a0, a1, a2, a3, b.x, b.y);
        }
    }

    float sl[4] = {0.f, 0.f, 0.f, 0.f}, dl[4] = {0.f, 0.f, 0.f, 0.f};
    float sh[4] = {0.f, 0.f, 0.f, 0.f}, dh[4] = {0.f, 0.f, 0.f, 0.f};
    bool wlo = rlo < N_NODES, whi = rhi < N_NODES;
    #pragma unroll
    for (int n = 0; n < 16; n++) {
        int col = 8 * n + 2 * q;
        int h = n >> 2;
        float as0 = __ldg(att_src + col), as1 = __ldg(att_src + col + 1);
        float ad0 = __ldg(att_dst + col), ad1 = __ldg(att_dst + col + 1);
        if (wlo)
            *(__half2*)(g_xh_h + (size_t)rlo * HC + col) =
                __floats2half2_rn(c[n][0], c[n][1]);
        if (whi)
            *(__half2*)(g_xh_h + (size_t)rhi * HC + col) =
                __floats2half2_rn(c[n][2], c[n][3]);
        sl[h] += c[n][0] * as0 + c[n][1] * as1;
        dl[h] += c[n][0] * ad0 + c[n][1] * ad1;
        sh[h] += c[n][2] * as0 + c[n][3] * as1;
        dh[h] += c[n][2] * ad0 + c[n][3] * ad1;
    }
    #pragma unroll
    for (int h = 0; h < 4; h++) {
        #pragma unroll
        for (int o = 1; o < 4; o <<= 1) {
            sl[h] += __shfl_xor_sync(0xffffffffu, sl[h], o);
            dl[h] += __shfl_xor_sync(0xffffffffu, dl[h], o);
            sh[h] += __shfl_xor_sync(0xffffffffu, sh[h], o);
            dh[h] += __shfl_xor_sync(0xffffffffu, dh[h], o);
        }
    }
    if (q == 0) {
        #pragma unroll
        for (int h = 0; h < 4; h++) {
            if (wlo) { g_asrc[rlo * HEADS + h] = sl[h]; g_adst[rlo * HEADS + h] = dl[h]; }
            if (whi) { g_asrc[rhi * HEADS + h] = sh[h]; g_adst[rhi * HEADS + h] = dh[h]; }
        }
    }
}

// ---------------- scan step 1: per-1024-block exclusive scan ---------------
__global__ __launch_bounds__(256) void k_scan1() {
    int b = blockIdx.x;
    int base = b * SCAN_BLK;
    int tid = threadIdx.x;
    int lane = tid & 31, w = tid >> 5;
    int v[4], ts = 0;
    #pragma unroll
    for (int j = 0; j < 4; j++) {
        int idx = base + tid * 4 + j;
        v[j] = (idx < N_NODES) ? g_count[idx] : 0;
        ts += v[j];
    }
    int incl = ts;
    #pragma unroll
    for (int o = 1; o < 32; o <<= 1) {
        int t = __shfl_up_sync(0xffffffffu, incl, o);
        if (lane >= o) incl += t;
    }
    __shared__ int wsum[8];
    if (lane == 31) wsum[w] = incl;
    __syncthreads();
    if (w == 0 && lane < 8) {
        int t = wsum[lane];
        #pragma unroll
        for (int o = 1; o < 8; o <<= 1) {
            int u = __shfl_up_sync(0xffu, t, o);
            if (lane >= o) t += u;
        }
        wsum[lane] = t;
    }
    __syncthreads();
    int excl = incl - ts + (w > 0 ? wsum[w - 1] : 0);
    int run = excl;
    #pragma unroll
    for (int j = 0; j < 4; j++) {
        int idx = base + tid * 4 + j;
        if (idx < N_NODES) g_rowptr[idx] = run;
        run += v[j];
    }
    __syncthreads();
    if (tid == 255) g_bsum[b] = wsum[7];
}

// ---------------- scan step 2: warp-parallel scan of 98 block sums ---------
__global__ void k_scan2() {
    int lane = threadIdx.x;            // 32 threads
    int run = 0;
    for (int b0 = 0; b0 < N_SCAN_BLKS; b0 += 32) {
        int i = b0 + lane;
        int v = (i < N_SCAN_BLKS) ? g_bsum[i] : 0;
        int incl = v;
        #pragma unroll
        for (int o = 1; o < 32; o <<= 1) {
            int t = __shfl_up_sync(0xffffffffu, incl, o);
            if (lane >= o) incl += t;
        }
        if (i < N_SCAN_BLKS) g_boff[i] = run + incl - v;
        run += __shfl_sync(0xffffffffu, incl, 31);
    }
    if (lane == 0) g_rowptr[N_NODES] = N_EDGES;
}

// ---------------- scan step 3: add offsets, init cursors -------------------
__global__ void k_scan3() {
    int i = blockIdx.x * blockDim.x + threadIdx.x;
    if (i >= N_NODES) return;
    int r = g_rowptr[i] + g_boff[i >> 10];
    g_rowptr[i] = r;
    g_cursor[i] = r;
}

// ---------------- scatter: leaky+exp+CSR scatter (post-join, light) --------
__global__ __launch_bounds__(256) void k_scatter2(const int* __restrict__ ei) {
    int e = blockIdx.x * 256 + threadIdx.x;
    if (e >= N_EDGES) return;
    int src = __ldg(ei + e);
    int dst = __ldg(ei + N_EDGES + e);
    float4 ae = __ldg(g_aedge + e);
    float4 as = __ldg((const float4*)(g_asrc) + src);
    float4 ad = __ldg((const float4*)(g_adst) + dst);
    float l0 = as.x + ad.x + ae.x;
    float l1 = as.y + ad.y + ae.y;
    float l2 = as.z + ad.z + ae.z;
    float l3 = as.w + ad.w + ae.w;
    l0 = l0 >= 0.f ? l0 : NEG_SLOPE * l0;
    l1 = l1 >= 0.f ? l1 : NEG_SLOPE * l1;
    l2 = l2 >= 0.f ? l2 : NEG_SLOPE * l2;
    l3 = l3 >= 0.f ? l3 : NEG_SLOPE * l3;
    __half2 p0 = __floats2half2_rn(__expf(l0), __expf(l1));
    __half2 p1 = __floats2half2_rn(__expf(l2), __expf(l3));
    int pos = atomicAdd(&g_cursor[dst], 1);
    uint4 rec;
    rec.x = (unsigned)src;
    rec.y = *(unsigned*)&p0;
    rec.z = *(unsigned*)&p1;
    rec.w = 0u;
    g_rec[pos] = rec;          // single STG.128
}

// ---------------- aggregate: lane-per-(head,4ch), pipelined rec loads ------
__global__ __launch_bounds__(256) void k_agg(float* __restrict__ out,
                                             const float* __restrict__ gat_bias,
                                             const float* __restrict__ bias) {
    int n = blockIdx.x * 8 + (threadIdx.x >> 5);
    if (n >= N_NODES) return;
    int lane = threadIdx.x & 31;
    int h  = lane >> 3;            // head owned by this lane
    int c0 = 4 * (lane & 7);       // channel base (0..28)
    int beg = g_rowptr[n];
    int end = g_rowptr[n + 1];
    float a0 = 0.f, a1 = 0.f, a2 = 0.f, a3 = 0.f, dsum = 0.f;
    uint4 r = (beg < end) ? __ldg(g_rec + beg) : make_uint4(0, 0, 0, 0);
    for (int idx = beg; idx < end; idx++) {
        uint4 rn = (idx + 1 < end) ? __ldg(g_rec + idx + 1) : r;   // prefetch
        int src = (int)r.x;
        unsigned evbits = (h & 2) ? r.z : r.y;
        float2 evp = __half22float2(*(__half2*)&evbits);
        float ev = (h & 1) ? evp.y : evp.x;
        uint2 xw = __ldg((const uint2*)(g_xh_h + (size_t)src * HC) + lane);
        float2 f0 = __half22float2(*(__half2*)&xw.x);
        float2 f1 = __half22float2(*(__half2*)&xw.y);
        a0 += ev * f0.x; a1 += ev * f0.y;
        a2 += ev * f1.x; a3 += ev * f1.y;
        dsum += ev;
        r = rn;
    }
    float inv = dsum > 0.f ? 1.f / dsum : 0.f;
    a0 *= inv; a1 *= inv; a2 *= inv; a3 *= inv;
    #pragma unroll
    for (int o = 8; o < 32; o <<= 1) {
        a0 += __shfl_xor_sync(0xffffffffu, a0, o);
        a1 += __shfl_xor_sync(0xffffffffu, a1, o);
        a2 += __shfl_xor_sync(0xffffffffu, a2, o);
        a3 += __shfl_xor_sync(0xffffffffu, a3, o);
    }
    if (lane < 8) {
        float rr[4] = {a0, a1, a2, a3};
        float4 v4;
        float* vp = (float*)&v4;
        #pragma unroll
        for (int j = 0; j < 4; j++) {
            int c = c0 + j;
            float gb = 0.25f * (__ldg(gat_bias + c)      + __ldg(gat_bias + 32 + c) +
                                __ldg(gat_bias + 64 + c) + __ldg(gat_bias + 96 + c));
            float v = 0.25f * rr[j] + gb + __ldg(bias + c);
            vp[j] = v > 0.f ? v : 0.f;
        }
        *(float4*)(out + (size_t)n * CH + c0) = v4;
    }
}

extern "C" void kernel_launch(void* const* d_in, const int* in_sizes, int n_in,
                              void* d_out, int out_size) {
    const float* x        = (const float*)d_in[0];
    const int*   ei       = (const int*)  d_in[1];
    const float* ea       = (const float*)d_in[2];
    const float* W        = (const float*)d_in[3];
    const float* att_src  = (const float*)d_in[4];
    const float* att_dst  = (const float*)d_in[5];
    const float* W_edge   = (const float*)d_in[6];
    const float* att_edge = (const float*)d_in[7];
    const float* gat_bias = (const float*)d_in[8];
    const float* bias     = (const float*)d_in[9];
    float* out = (float*)d_out;

    // one-time resource creation (streams/events are resources, not work)
    static cudaStream_t s_csr = 0, s_edge = 0;
    static cudaEvent_t  ev_fork = 0, ev_csr = 0, ev_edge = 0;
    if (s_csr == 0) {
        cudaStreamCreateWithFlags(&s_csr, cudaStreamNonBlocking);
        cudaStreamCreateWithFlags(&s_edge, cudaStreamNonBlocking);
        cudaEventCreateWithFlags(&ev_fork, cudaEventDisableTiming);
        cudaEventCreateWithFlags(&ev_csr, cudaEventDisableTiming);
        cudaEventCreateWithFlags(&ev_edge, cudaEventDisableTiming);
    }

    // fork
    cudaEventRecord(ev_fork, 0);
    cudaStreamWaitEvent(s_csr, ev_fork, 0);
    cudaStreamWaitEvent(s_edge, ev_fork, 0);

    // CSR chain (aux1)
    k_init <<<(N_NODES + 255) / 256, 256, 0, s_csr>>>();
    k_count<<<(N_EDGES / 4 + 255) / 256, 256, 0, s_csr>>>(ei);
    k_scan1<<<N_SCAN_BLKS, 256, 0, s_csr>>>();
    k_scan2<<<1, 32, 0, s_csr>>>();
    k_scan3<<<(N_NODES + 255) / 256, 256, 0, s_csr>>>();
    cudaEventRecord(ev_csr, s_csr);

    // edge-attr chain (aux2): weff -> aedge (the 205MB read, off critical path)
    k_weff <<<1, 128, 0, s_edge>>>(W_edge, att_edge);
    k_aedge<<<N_EDGES / 256, 256, 0, s_edge>>>(ea);
    cudaEventRecord(ev_edge, s_edge);

    // main: wpack -> gemm
    k_wpack<<<32, 256>>>(W);
    k_gemm <<<(N_NODES + 127) / 128, 256>>>(x, att_src, att_dst);

    // join: scatter needs gemm (asrc/adst) + cursors + aedge
    cudaStreamWaitEvent(0, ev_csr, 0);
    cudaStreamWaitEvent(0, ev_edge, 0);
    k_scatter2<<<(N_EDGES + 255) / 256, 256>>>(ei);
    k_agg     <<<(N_NODES + 7) / 8, 256>>>(out, gat_bias, bias);
}